// round 2
// baseline (speedup 1.0000x reference)
#include <cuda_runtime.h>

#define Bc 2
#define Tc 2048
#define Cc 512
#define Hc 8
#define HDc 64
#define TOPKc 64
#define BHc (Bc*Hc)
#define Mr (Bc*Tc)
#define QT 4

// Scratch (allocations are forbidden; device globals are the sanctioned path)
__device__ float g_Qh[BHc*Tc*HDc];
__device__ float g_Kh[BHc*Tc*HDc];
__device__ float g_Vh[BHc*Tc*HDc];
__device__ float g_Y [Bc*Tc*Cc];

// Order-preserving float<->uint transforms (strictly monotonic, injective)
__device__ __forceinline__ unsigned f2u(float f) {
    unsigned b = __float_as_uint(f);
    return b ^ ((unsigned)((int)b >> 31) | 0x80000000u);
}
__device__ __forceinline__ float u2f(unsigned u) {
    unsigned b = (u & 0x80000000u) ? (u ^ 0x80000000u) : ~u;
    return __uint_as_float(b);
}

// ---------------------------------------------------------------------------
// SGEMM: out(M=4096, N=512) = A(4096x512) @ W(512x512) + bias
// BM=128, BN=64, BK=8, 128 threads, 8x8 per-thread microtile.
// headMajor=1: scatter into (b, h, t, d) layout for Q/K/V heads.
// ---------------------------------------------------------------------------
__global__ void __launch_bounds__(128)
sgemm_kernel(const float* __restrict__ A, const float* __restrict__ W,
             const float* __restrict__ bias, float* __restrict__ out,
             int headMajor)
{
    const int K = Cc, N = Cc;
    __shared__ float As[8][128];
    __shared__ float Bs[8][64];

    int tid = threadIdx.x;
    int bm = blockIdx.y * 128;
    int bn = blockIdx.x * 64;
    int ty = tid >> 3;     // 0..15 -> rows (x8)
    int tx = tid & 7;      // 0..7  -> cols (x8)

    float acc[8][8];
    #pragma unroll
    for (int i = 0; i < 8; i++)
        #pragma unroll
        for (int j = 0; j < 8; j++) acc[i][j] = 0.f;

    const float4* aP = reinterpret_cast<const float4*>(A + (size_t)(bm + tid) * K);
    int brow = tid >> 4;           // 0..7
    int bcol = (tid & 15) << 2;    // 0..60

    for (int kb = 0; kb < K; kb += 8) {
        float4 a0 = aP[(kb >> 2)];
        float4 a1 = aP[(kb >> 2) + 1];
        float4 bv = *reinterpret_cast<const float4*>(W + (size_t)(kb + brow) * N + bn + bcol);
        __syncthreads();
        As[0][tid] = a0.x; As[1][tid] = a0.y; As[2][tid] = a0.z; As[3][tid] = a0.w;
        As[4][tid] = a1.x; As[5][tid] = a1.y; As[6][tid] = a1.z; As[7][tid] = a1.w;
        *reinterpret_cast<float4*>(&Bs[brow][bcol]) = bv;
        __syncthreads();
        #pragma unroll
        for (int k = 0; k < 8; k++) {
            float a[8], b[8];
            #pragma unroll
            for (int i = 0; i < 8; i++) a[i] = As[k][ty * 8 + i];
            #pragma unroll
            for (int j = 0; j < 8; j++) b[j] = Bs[k][tx * 8 + j];
            #pragma unroll
            for (int i = 0; i < 8; i++)
                #pragma unroll
                for (int j = 0; j < 8; j++) acc[i][j] += a[i] * b[j];
        }
    }

    #pragma unroll
    for (int i = 0; i < 8; i++) {
        int m = bm + ty * 8 + i;
        int b = m >> 11;             // / Tc
        int t = m & (Tc - 1);
        #pragma unroll
        for (int j = 0; j < 8; j++) {
            int n = bn + tx * 8 + j;
            float v = acc[i][j] + bias[n];
            if (headMajor) {
                int h = n >> 6, d = n & 63;
                out[((size_t)((b * Hc + h) * Tc + t) << 6) + d] = v;
            } else {
                out[(size_t)m * N + n] = v;
            }
        }
    }
}

// ---------------------------------------------------------------------------
// V normalization: one warp per (b,h,t) row of 64 elements.
// vh = vh / max(||vh||, 1e-12)
// ---------------------------------------------------------------------------
__global__ void vnorm_kernel(float* __restrict__ V)
{
    int row = blockIdx.x * 8 + (threadIdx.x >> 5);
    int lane = threadIdx.x & 31;
    float2* vr = reinterpret_cast<float2*>(V + (size_t)row * HDc);
    float2 v = vr[lane];
    float ss = v.x * v.x + v.y * v.y;
    #pragma unroll
    for (int off = 16; off; off >>= 1) ss += __shfl_xor_sync(0xffffffffu, ss, off);
    float scale = 1.0f / fmaxf(sqrtf(ss), 1e-12f);
    v.x *= scale; v.y *= scale;
    vr[lane] = v;
}

// ---------------------------------------------------------------------------
// Attention: per block QT=4 consecutive query rows of one (b,h).
// 512 threads, 128 per row. Phases: scores -> exact rank-64 radix select ->
// deterministic compaction -> softmax over survivors -> sparse PV.
// ---------------------------------------------------------------------------
struct AttnSmem {
    float          qs[QT][HDc];
    unsigned       su[QT][Tc];        // scores as order-preserving uints; later softmax probs
    float          ybuf[QT][128];
    unsigned       s_red[QT][4];
    float          s_fred[QT][4];
    int            s_wsum[QT][4];
    unsigned short sidx[QT][Tc];      // survivor key indices
};

__global__ void __launch_bounds__(512)
attn_kernel(const float* __restrict__ Q, const float* __restrict__ K,
            const float* __restrict__ V, float* __restrict__ Y)
{
    extern __shared__ unsigned char smem_raw[];
    AttnSmem* S = reinterpret_cast<AttnSmem*>(smem_raw);

    int tid   = threadIdx.x;
    int row   = tid >> 7;          // 0..3 (query row within block)
    int rt    = tid & 127;         // thread within row
    int lane  = tid & 31;
    int rwarp = (tid >> 5) & 3;    // warp within row

    int bh = blockIdx.y;
    int qi = blockIdx.x * QT + row;
    int n  = qi + 1;               // causal: keys 0..qi valid

    const float* Qr = Q + (size_t)(bh * Tc + qi) * HDc;
    const float* Kb = K + (size_t)bh * Tc * HDc;
    const float* Vb = V + (size_t)bh * Tc * HDc;

    if (rt < HDc) S->qs[row][rt] = Qr[rt];
    __syncthreads();

    // ---- Phase B: scores s[k] = (q . k_k) * 0.125, stored as ordered uints
    const float4* q4 = reinterpret_cast<const float4*>(S->qs[row]);
    for (int k = rt; k < n; k += 128) {
        const float4* k4 = reinterpret_cast<const float4*>(Kb + (size_t)k * HDc);
        float acc = 0.f;
        #pragma unroll
        for (int i = 0; i < 16; i++) {
            float4 kv = k4[i], qv = q4[i];
            acc += kv.x * qv.x + kv.y * qv.y + kv.z * qv.z + kv.w * qv.w;
        }
        S->su[row][k] = f2u(acc * 0.125f);
    }
    __syncthreads();

    // ---- Phase C: exact 64th-largest via 32-pass MSB binary search.
    // Always executed by all threads (uniform __syncthreads); result ignored
    // for n <= TOPK rows.
    unsigned prefix = 0; int need = TOPKc;
    #pragma unroll 1
    for (int bit = 31; bit >= 0; --bit) {
        unsigned test = prefix | (1u << bit);
        unsigned msk  = ~((1u << bit) - 1u);
        int cnt = 0;
        for (int k = rt; k < n; k += 128)
            cnt += ((S->su[row][k] & msk) == test) ? 1 : 0;
        #pragma unroll
        for (int off = 16; off; off >>= 1) cnt += __shfl_xor_sync(0xffffffffu, cnt, off);
        if (lane == 0) S->s_red[row][rwarp] = (unsigned)cnt;
        __syncthreads();
        cnt = (int)(S->s_red[row][0] + S->s_red[row][1] + S->s_red[row][2] + S->s_red[row][3]);
        __syncthreads();
        if (cnt >= need) prefix = test; else need -= cnt;
    }
    unsigned thrU = (n > TOPKc) ? prefix : 0u;   // keep all when row shorter than TOPK

    // ---- Phase D: deterministic compaction (count + scan + ordered write), plus max
    int cloc = 0; unsigned umax = 0u;
    for (int k = rt; k < n; k += 128) {
        unsigned u = S->su[row][k];
        umax = max(umax, u);
        cloc += (u >= thrU) ? 1 : 0;
    }
    int inc = cloc;
    #pragma unroll
    for (int off = 1; off < 32; off <<= 1) {
        int v = __shfl_up_sync(0xffffffffu, inc, off);
        if (lane >= off) inc += v;
    }
    if (lane == 31) S->s_wsum[row][rwarp] = inc;
    #pragma unroll
    for (int off = 16; off; off >>= 1) umax = max(umax, __shfl_xor_sync(0xffffffffu, umax, off));
    if (lane == 0) S->s_red[row][rwarp] = umax;
    __syncthreads();
    int wbase = 0;
    #pragma unroll
    for (int w = 0; w < 4; w++) if (w < rwarp) wbase += S->s_wsum[row][w];
    int m = S->s_wsum[row][0] + S->s_wsum[row][1] + S->s_wsum[row][2] + S->s_wsum[row][3];
    umax = max(max(S->s_red[row][0], S->s_red[row][1]),
               max(S->s_red[row][2], S->s_red[row][3]));
    int pos = wbase + inc - cloc;  // exclusive prefix for this thread
    for (int k = rt; k < n; k += 128) {
        if (S->su[row][k] >= thrU) S->sidx[row][pos++] = (unsigned short)k;
    }
    __syncthreads();

    // ---- Phase F: softmax numerator + sum over survivors (probs overwrite su in place)
    float maxf = u2f(umax);
    float lsum = 0.f;
    for (int j = rt; j < m; j += 128) {
        int k = S->sidx[row][j];
        float p = __expf(u2f(S->su[row][k]) - maxf);
        S->su[row][k] = __float_as_uint(p);
        lsum += p;
    }
    #pragma unroll
    for (int off = 16; off; off >>= 1) lsum += __shfl_xor_sync(0xffffffffu, lsum, off);
    if (lane == 0) S->s_fred[row][rwarp] = lsum;
    __syncthreads();
    float sum = S->s_fred[row][0] + S->s_fred[row][1] + S->s_fred[row][2] + S->s_fred[row][3];
    float rinv = 1.0f / sum;

    // ---- Phase G: sparse PV over ~64 survivors. threads = (d, part)
    int d = rt & 63, part = rt >> 6;
    float acc = 0.f;
    for (int j = part; j < m; j += 2) {
        int k = S->sidx[row][j];
        acc += __uint_as_float(S->su[row][k]) * Vb[(size_t)k * HDc + d];
    }
    S->ybuf[row][rt] = acc;
    __syncthreads();
    if (rt < 64) {
        float y = (S->ybuf[row][rt] + S->ybuf[row][rt + 64]) * rinv;
        int b = bh >> 3, h = bh & 7;   // bh = b*H + h
        Y[(size_t)(b * Tc + qi) * Cc + h * HDc + rt] = y;
    }
}

// ---------------------------------------------------------------------------
extern "C" void kernel_launch(void* const* d_in, const int* in_sizes, int n_in,
                              void* d_out, int out_size)
{
    // metadata order: q, tgt_mask, Wq, bq, Wk, bk, Wv, bv, Wp, bp
    const float* q  = (const float*)d_in[0];
    // d_in[1] = tgt_mask (causal; structure known, not read)
    const float* Wq = (const float*)d_in[2];
    const float* bq = (const float*)d_in[3];
    const float* Wk = (const float*)d_in[4];
    const float* bk = (const float*)d_in[5];
    const float* Wv = (const float*)d_in[6];
    const float* bv = (const float*)d_in[7];
    const float* Wp = (const float*)d_in[8];
    const float* bp = (const float*)d_in[9];

    float *Qh, *Kh, *Vh, *Yb;
    cudaGetSymbolAddress((void**)&Qh, g_Qh);
    cudaGetSymbolAddress((void**)&Kh, g_Kh);
    cudaGetSymbolAddress((void**)&Vh, g_Vh);
    cudaGetSymbolAddress((void**)&Yb, g_Y);

    cudaFuncSetAttribute(attn_kernel, cudaFuncAttributeMaxDynamicSharedMemorySize,
                         (int)sizeof(AttnSmem));

    dim3 gg(Cc / 64, Mr / 128);   // (8, 32)
    sgemm_kernel<<<gg, 128>>>(q, Wq, bq, Qh, 1);
    sgemm_kernel<<<gg, 128>>>(q, Wk, bk, Kh, 1);
    sgemm_kernel<<<gg, 128>>>(q, Wv, bv, Vh, 1);
    vnorm_kernel<<<(BHc * Tc) / 8, 256>>>(Vh);
    attn_kernel<<<dim3(Tc / QT, BHc), 512, sizeof(AttnSmem)>>>(Qh, Kh, Vh, Yb);
    sgemm_kernel<<<gg, 128>>>(Yb, Wp, bp, (float*)d_out, 0);
}

// round 3
// speedup vs baseline: 4.1362x; 4.1362x over previous
#include <cuda_runtime.h>

#define Bc 2
#define Tc 2048
#define Cc 512
#define Hc 8
#define HDc 64
#define TOPKc 64
#define BHc (Bc*Hc)
#define Mr (Bc*Tc)
#define QT 8
#define KT 128

typedef unsigned long long ull;

// Scratch (device globals; allocations forbidden)
__device__ float g_Qh[BHc*Tc*HDc];
__device__ float g_Kh[BHc*Tc*HDc];
__device__ float g_Vh[BHc*Tc*HDc];
__device__ float g_Y [Bc*Tc*Cc];

// ---------------------------------------------------------------------------
// helpers
// ---------------------------------------------------------------------------
__device__ __forceinline__ unsigned f2u(float f) {
    unsigned b = __float_as_uint(f);
    return b ^ ((unsigned)((int)b >> 31) | 0x80000000u);
}
__device__ __forceinline__ float u2f(unsigned u) {
    unsigned b = (u & 0x80000000u) ? (u ^ 0x80000000u) : ~u;
    return __uint_as_float(b);
}
__device__ __forceinline__ ull packdup(float x) {
    ull d; asm("mov.b64 %0, {%1, %1};" : "=l"(d) : "f"(x)); return d;
}
__device__ __forceinline__ ull packpair(float x, float y) {
    ull d; asm("mov.b64 %0, {%1, %2};" : "=l"(d) : "f"(x), "f"(y)); return d;
}
__device__ __forceinline__ void fma2(ull& d, ull a, ull b, ull c) {
    asm("fma.rn.f32x2 %0, %1, %2, %3;" : "=l"(d) : "l"(a), "l"(b), "l"(c));
}
__device__ __forceinline__ float2 unpack2(ull v) {
    float x, y; asm("mov.b64 {%0, %1}, %2;" : "=f"(x), "=f"(y) : "l"(v));
    return make_float2(x, y);
}

// ---------------------------------------------------------------------------
// SGEMM: out(4096,512) = A(4096x512) @ W(512x512) + bias
// BM=BN=128, BK=8, 256 threads, 8x8 micro (split 4+4), f32x2 FMA, double buffer.
// ---------------------------------------------------------------------------
__global__ void __launch_bounds__(256, 2)
sgemm_kernel(const float* __restrict__ A, const float* __restrict__ W,
             const float* __restrict__ bias, float* __restrict__ out,
             int headMajor)
{
    __shared__ float As[2][8][128];
    __shared__ float Bs[2][8][128];

    int tid = threadIdx.x;
    int bm = blockIdx.y * 128;
    int bn = blockIdx.x * 128;
    int ty = tid >> 4;            // 0..15
    int tx = tid & 15;            // 0..15

    int arow = tid >> 1;          // 0..127
    int akq  = (tid & 1) * 4;     // 0 or 4
    int brow = tid >> 5;          // 0..7
    int bcol = (tid & 31) * 4;    // 0..124

    const float* Ag = A + (size_t)(bm + arow) * Cc + akq;
    const float* Wg = W + (size_t)brow * Cc + bn + bcol;

    ull acc[8][4];
    #pragma unroll
    for (int i = 0; i < 8; i++)
        #pragma unroll
        for (int j = 0; j < 4; j++) acc[i][j] = 0ULL;

    // preload tile 0
    {
        float4 av = *reinterpret_cast<const float4*>(Ag);
        float4 bv = *reinterpret_cast<const float4*>(Wg);
        As[0][akq + 0][arow] = av.x;
        As[0][akq + 1][arow] = av.y;
        As[0][akq + 2][arow] = av.z;
        As[0][akq + 3][arow] = av.w;
        *reinterpret_cast<float4*>(&Bs[0][brow][bcol]) = bv;
    }
    __syncthreads();

    #pragma unroll 1
    for (int kb = 0; kb < 64; kb++) {
        int cur = kb & 1;
        float4 an, bnv;
        if (kb < 63) {
            an  = *reinterpret_cast<const float4*>(Ag + (kb + 1) * 8);
            bnv = *reinterpret_cast<const float4*>(Wg + (size_t)(kb + 1) * 8 * Cc);
        }
        #pragma unroll
        for (int k = 0; k < 8; k++) {
            float4 a0 = *reinterpret_cast<const float4*>(&As[cur][k][ty * 4]);
            float4 a1 = *reinterpret_cast<const float4*>(&As[cur][k][64 + ty * 4]);
            float4 b0 = *reinterpret_cast<const float4*>(&Bs[cur][k][tx * 4]);
            float4 b1 = *reinterpret_cast<const float4*>(&Bs[cur][k][64 + tx * 4]);
            ull bb[4] = { packpair(b0.x, b0.y), packpair(b0.z, b0.w),
                          packpair(b1.x, b1.y), packpair(b1.z, b1.w) };
            ull aa[8] = { packdup(a0.x), packdup(a0.y), packdup(a0.z), packdup(a0.w),
                          packdup(a1.x), packdup(a1.y), packdup(a1.z), packdup(a1.w) };
            #pragma unroll
            for (int i = 0; i < 8; i++)
                #pragma unroll
                for (int j = 0; j < 4; j++)
                    fma2(acc[i][j], aa[i], bb[j], acc[i][j]);
        }
        if (kb < 63) {
            int nxt = cur ^ 1;
            As[nxt][akq + 0][arow] = an.x;
            As[nxt][akq + 1][arow] = an.y;
            As[nxt][akq + 2][arow] = an.z;
            As[nxt][akq + 3][arow] = an.w;
            *reinterpret_cast<float4*>(&Bs[nxt][brow][bcol]) = bnv;
            __syncthreads();
        }
    }

    // epilogue
    float4 bia0 = *reinterpret_cast<const float4*>(bias + bn + tx * 4);
    float4 bia1 = *reinterpret_cast<const float4*>(bias + bn + 64 + tx * 4);
    #pragma unroll
    for (int i = 0; i < 8; i++) {
        int r = (i < 4) ? (ty * 4 + i) : (64 + ty * 4 + (i - 4));
        int mrow = bm + r;
        int b = mrow >> 11;
        int t = mrow & (Tc - 1);
        float2 c0 = unpack2(acc[i][0]);
        float2 c1 = unpack2(acc[i][1]);
        float2 c2 = unpack2(acc[i][2]);
        float2 c3 = unpack2(acc[i][3]);
        float4 o0 = make_float4(c0.x + bia0.x, c0.y + bia0.y, c1.x + bia0.z, c1.y + bia0.w);
        float4 o1 = make_float4(c2.x + bia1.x, c2.y + bia1.y, c3.x + bia1.z, c3.y + bia1.w);
        if (headMajor) {
            int n0 = bn + tx * 4;       int h0 = n0 >> 6, d0 = n0 & 63;
            int n1 = bn + 64 + tx * 4;  int h1 = n1 >> 6, d1 = n1 & 63;
            *reinterpret_cast<float4*>(out + ((size_t)((b * Hc + h0) * Tc + t) << 6) + d0) = o0;
            *reinterpret_cast<float4*>(out + ((size_t)((b * Hc + h1) * Tc + t) << 6) + d1) = o1;
        } else {
            *reinterpret_cast<float4*>(out + (size_t)mrow * Cc + bn + tx * 4) = o0;
            *reinterpret_cast<float4*>(out + (size_t)mrow * Cc + bn + 64 + tx * 4) = o1;
        }
    }
}

// ---------------------------------------------------------------------------
// V normalization: one warp per (b,h,t) row of 64 elements.
// ---------------------------------------------------------------------------
__global__ void vnorm_kernel(float* __restrict__ V)
{
    int row = blockIdx.x * 8 + (threadIdx.x >> 5);
    int lane = threadIdx.x & 31;
    float2* vr = reinterpret_cast<float2*>(V + (size_t)row * HDc);
    float2 v = vr[lane];
    float ss = v.x * v.x + v.y * v.y;
    #pragma unroll
    for (int off = 16; off; off >>= 1) ss += __shfl_xor_sync(0xffffffffu, ss, off);
    float scale = 1.0f / fmaxf(sqrtf(ss), 1e-12f);
    v.x *= scale; v.y *= scale;
    vr[lane] = v;
}

// ---------------------------------------------------------------------------
// Attention: QT=8 query rows per block, 8 warps (warp <-> row).
// K tiled through SMEM (coalesced, conflict-free), warp-local 4-pass byte
// radix select (exact rank-64), ballot compaction, sparse PV.
// ---------------------------------------------------------------------------
struct AttnSmem {
    float qs[QT][HDc];                 // 2 KB
    float kt[KT][68];                  // 34816 B (stride-68 pad)
    unsigned su[QT][Tc];               // 64 KB: scores as ordered uints / probs
    union RowSel {
        int hist[256];                 // during radix select
        unsigned short sidx[512];      // after: survivor indices
    } sel[QT];                         // 8 KB
};

__global__ void __launch_bounds__(256, 2)
attn_kernel(const float* __restrict__ Q, const float* __restrict__ K,
            const float* __restrict__ V, float* __restrict__ Y)
{
    extern __shared__ unsigned char raw[];
    AttnSmem* S = reinterpret_cast<AttnSmem*>(raw);

    int tid  = threadIdx.x;
    int warp = tid >> 5;
    int lane = tid & 31;

    int bh = blockIdx.y;
    int qbase = ((int)gridDim.x - 1 - (int)blockIdx.x) * QT;  // long rows first
    int qi = qbase + warp;
    int n  = qi + 1;
    int n_max = qbase + QT;

    const float* Kb = K + (size_t)bh * Tc * HDc;
    const float* Vb = V + (size_t)bh * Tc * HDc;

    if (tid < 128) {
        int r = tid >> 4, i = tid & 15;
        reinterpret_cast<float4*>(S->qs[r])[i] =
            reinterpret_cast<const float4*>(Q + ((size_t)bh * Tc + qbase + r) * HDc)[i];
    }
    const float4* q4 = reinterpret_cast<const float4*>(S->qs[warp]);

    // ---- scores via SMEM K tiles
    for (int t0 = 0; t0 < n_max; t0 += KT) {
        __syncthreads();
        #pragma unroll
        for (int i = 0; i < 8; i++) {
            int idx = tid + 256 * i;
            int kk = idx >> 4, dq = idx & 15;
            float4 v = *reinterpret_cast<const float4*>(Kb + (size_t)(t0 + kk) * HDc + dq * 4);
            *reinterpret_cast<float4*>(&S->kt[kk][dq * 4]) = v;
        }
        __syncthreads();

        float acc[4] = {0.f, 0.f, 0.f, 0.f};
        #pragma unroll
        for (int i = 0; i < 16; i++) {
            float4 qv = q4[i];
            #pragma unroll
            for (int j = 0; j < 4; j++) {
                float4 kv = *reinterpret_cast<const float4*>(&S->kt[lane + 32 * j][i * 4]);
                acc[j] += qv.x * kv.x + qv.y * kv.y + qv.z * kv.z + qv.w * kv.w;
            }
        }
        #pragma unroll
        for (int j = 0; j < 4; j++) {
            int kk = t0 + lane + 32 * j;
            if (kk <= qi) S->su[warp][kk] = f2u(acc[j] * 0.125f);
        }
    }
    // after this point everything is warp-local (warp w owns row w)

    // ---- exact rank-64 threshold: 4-pass byte radix (warp-local)
    unsigned thrU = 0u;
    if (n > TOPKc) {
        unsigned pref = 0u; int need = TOPKc;
        #pragma unroll 1
        for (int by = 3; by >= 0; --by) {
            int sh = by * 8;
            #pragma unroll
            for (int b = lane; b < 256; b += 32) S->sel[warp].hist[b] = 0;
            __syncwarp();
            if (by == 3) {
                for (int k = lane; k < n; k += 32) {
                    unsigned u = S->su[warp][k];
                    atomicAdd(&S->sel[warp].hist[u >> 24], 1);
                }
            } else {
                unsigned hp = pref >> (sh + 8);
                for (int k = lane; k < n; k += 32) {
                    unsigned u = S->su[warp][k];
                    if ((u >> (sh + 8)) == hp)
                        atomicAdd(&S->sel[warp].hist[(u >> sh) & 255u], 1);
                }
            }
            __syncwarp();
            // lane L owns bins [248-8L, 255-8L]; suffix counts from the top
            int s = 0;
            #pragma unroll
            for (int j = 0; j < 8; j++) s += S->sel[warp].hist[255 - lane * 8 - j];
            int cum = s;
            #pragma unroll
            for (int off = 1; off < 32; off <<= 1) {
                int v = __shfl_up_sync(0xffffffffu, cum, off);
                if (lane >= off) cum += v;
            }
            unsigned bal = __ballot_sync(0xffffffffu, cum >= need);
            int selL = __ffs(bal) - 1;
            int above = __shfl_sync(0xffffffffu, cum - s, selL);
            int sneed = need - above;
            int res = 0;
            if (lane == selL) {
                int c = 0;
                #pragma unroll 1
                for (int j = 0; j < 8; j++) {
                    int b = 255 - selL * 8 - j;
                    int h = S->sel[warp].hist[b];
                    if (c + h >= sneed) { res = (b << 16) | (sneed - c); break; }
                    c += h;
                }
            }
            res = __shfl_sync(0xffffffffu, res, selL);
            pref |= (unsigned)(res >> 16) << sh;
            need = res & 0xffff;
        }
        thrU = pref;
    }
    __syncwarp();

    // ---- ballot compaction (ordered, deterministic) + row max
    int m = 0; unsigned umax = 0u;
    for (int k0 = 0; k0 < n; k0 += 32) {
        int k = k0 + lane;
        bool a = k < n;
        unsigned u = a ? S->su[warp][k] : 0u;
        umax = max(umax, u);
        bool keep = a && (u >= thrU);
        unsigned bal = __ballot_sync(0xffffffffu, keep);
        if (keep) {
            int pos = m + __popc(bal & ((1u << lane) - 1u));
            if (pos < 512) S->sel[warp].sidx[pos] = (unsigned short)k;
        }
        m += __popc(bal);
    }
    if (m > 512) m = 512;
    #pragma unroll
    for (int off = 16; off; off >>= 1)
        umax = max(umax, __shfl_xor_sync(0xffffffffu, umax, off));

    // ---- softmax over survivors (probs overwrite su in place)
    float maxf = u2f(umax);
    float lsum = 0.f;
    for (int j = lane; j < m; j += 32) {
        int k = S->sel[warp].sidx[j];
        float p = __expf(u2f(S->su[warp][k]) - maxf);
        S->su[warp][k] = __float_as_uint(p);
        lsum += p;
    }
    __syncwarp();
    #pragma unroll
    for (int off = 16; off; off >>= 1) lsum += __shfl_xor_sync(0xffffffffu, lsum, off);
    float rinv = 1.0f / lsum;

    // ---- sparse PV: lane owns d = {2*lane, 2*lane+1}; unroll 4 for MLP
    const float2* V2 = reinterpret_cast<const float2*>(Vb);
    float2 y = make_float2(0.f, 0.f);
    int j = 0;
    for (; j + 4 <= m; j += 4) {
        int k0 = S->sel[warp].sidx[j + 0];
        int k1 = S->sel[warp].sidx[j + 1];
        int k2 = S->sel[warp].sidx[j + 2];
        int k3 = S->sel[warp].sidx[j + 3];
        float p0 = __uint_as_float(S->su[warp][k0]);
        float p1 = __uint_as_float(S->su[warp][k1]);
        float p2 = __uint_as_float(S->su[warp][k2]);
        float p3 = __uint_as_float(S->su[warp][k3]);
        float2 v0 = V2[(size_t)k0 * 32 + lane];
        float2 v1 = V2[(size_t)k1 * 32 + lane];
        float2 v2 = V2[(size_t)k2 * 32 + lane];
        float2 v3 = V2[(size_t)k3 * 32 + lane];
        y.x += p0 * v0.x + p1 * v1.x + p2 * v2.x + p3 * v3.x;
        y.y += p0 * v0.y + p1 * v1.y + p2 * v2.y + p3 * v3.y;
    }
    for (; j < m; j++) {
        int k = S->sel[warp].sidx[j];
        float p = __uint_as_float(S->su[warp][k]);
        float2 v = V2[(size_t)k * 32 + lane];
        y.x += p * v.x; y.y += p * v.y;
    }
    int b = bh >> 3, h = bh & 7;
    *reinterpret_cast<float2*>(Y + (size_t)(b * Tc + qi) * Cc + h * HDc + lane * 2) =
        make_float2(y.x * rinv, y.y * rinv);
}

// ---------------------------------------------------------------------------
extern "C" void kernel_launch(void* const* d_in, const int* in_sizes, int n_in,
                              void* d_out, int out_size)
{
    const float* q  = (const float*)d_in[0];
    const float* Wq = (const float*)d_in[2];
    const float* bq = (const float*)d_in[3];
    const float* Wk = (const float*)d_in[4];
    const float* bk = (const float*)d_in[5];
    const float* Wv = (const float*)d_in[6];
    const float* bv = (const float*)d_in[7];
    const float* Wp = (const float*)d_in[8];
    const float* bp = (const float*)d_in[9];

    float *Qh, *Kh, *Vh, *Yb;
    cudaGetSymbolAddress((void**)&Qh, g_Qh);
    cudaGetSymbolAddress((void**)&Kh, g_Kh);
    cudaGetSymbolAddress((void**)&Vh, g_Vh);
    cudaGetSymbolAddress((void**)&Yb, g_Y);

    cudaFuncSetAttribute(attn_kernel, cudaFuncAttributeMaxDynamicSharedMemorySize,
                         (int)sizeof(AttnSmem));

    dim3 gg(Cc / 128, Mr / 128);   // (4, 32)
    sgemm_kernel<<<gg, 256>>>(q, Wq, bq, Qh, 1);
    sgemm_kernel<<<gg, 256>>>(q, Wk, bk, Kh, 1);
    sgemm_kernel<<<gg, 256>>>(q, Wv, bv, Vh, 1);
    vnorm_kernel<<<(BHc * Tc) / 8, 256>>>(Vh);
    attn_kernel<<<dim3(Tc / QT, BHc), 256, sizeof(AttnSmem)>>>(Qh, Kh, Vh, Yb);
    sgemm_kernel<<<gg, 256>>>(Yb, Wp, bp, (float*)d_out, 0);
}